// round 17
// baseline (speedup 1.0000x reference)
#include <cuda_runtime.h>

#define NN 1024
#define DD 128
#define DH 64    // d-range per z-slice of pair_kernel

// ---------------------------------------------------------------------------
// Device scratch (allocation-free)
// ---------------------------------------------------------------------------
__device__ float g_PIBT[DD * NN];   // pi + b1, transposed [d][i]
__device__ float g_PJT [DD * NN];   // pj, transposed [d][j]
__device__ float g_W2H [DD];        // 0.5 * W2 (for pair)
__device__ float g_ci  [NN];
__device__ float g_cj  [NN];
__device__ float g_P1  [NN * NN];   // partial sums for d in [64,128)

// ---------------------------------------------------------------------------
// f32x2 packed helpers (sm_103a)
// ---------------------------------------------------------------------------
__device__ __forceinline__ unsigned long long pack2(float lo, float hi) {
    unsigned long long r;
    asm("mov.b64 %0, {%1, %2};" : "=l"(r) : "f"(lo), "f"(hi));
    return r;
}
__device__ __forceinline__ void unpack2(unsigned long long v, float& lo, float& hi) {
    asm("mov.b64 {%0, %1}, %2;" : "=f"(lo), "=f"(hi) : "l"(v));
}
__device__ __forceinline__ unsigned long long add2(unsigned long long a, unsigned long long b) {
    unsigned long long r;
    asm("add.rn.f32x2 %0, %1, %2;" : "=l"(r) : "l"(a), "l"(b));
    return r;
}
__device__ __forceinline__ unsigned long long fma2(unsigned long long a, unsigned long long b,
                                                   unsigned long long c) {
    unsigned long long r;
    asm("fma.rn.f32x2 %0, %1, %2, %3;" : "=l"(r) : "l"(a), "l"(b), "l"(c));
    return r;
}
#define ABS2_MASK 0x7FFFFFFF7FFFFFFFULL

// ---------------------------------------------------------------------------
// Kernel A (v8): prep v7 + fused ci/cj reduction (cicj kernel deleted).
// 128 blocks x 512 threads. Thread = (concat col dc = tid&255, half h),
// 4 rows each. z staged transposed (zsT[k][row], pad 12).
// Epilogue: w'*acc products staged in smem; 16 warps reduce 8 ci + 8 cj rows.
// ---------------------------------------------------------------------------
__global__ void __launch_bounds__(512, 1) prep_kernel(
    const float* __restrict__ z, const float* __restrict__ W1,
    const float* __restrict__ b1, const float* __restrict__ W2)
{
    __shared__ float zsT[DD][12];        // [k][row 0..7]
    __shared__ float cs[2][8][132];      // [pi/pj][row][d] products (8.4 KB)

    const int tid = threadIdx.x;         // 0..511
    const int dc  = tid & 255;           // concat output column
    const int h   = tid >> 8;            // 0/1 -> rows 4h..4h+3
    const int i0  = blockIdx.x * 8;

    if (blockIdx.x == 0 && tid < DD) g_W2H[tid] = 0.5f * W2[tid];

    #pragma unroll
    for (int t = 0; t < 2; t++) {
        const int idx = tid + t * 512;   // 0..1023
        const int r = idx >> 7;          // row 0..7
        const int k = idx & 127;
        zsT[k][r] = z[(i0 + r) * DD + k];
    }
    __syncthreads();

    const bool is_pi = (dc < DD);
    const int  d     = is_pi ? dc : dc - DD;
    const float* wcol = is_pi ? (W1 + d) : (W1 + DD * DD + d);
    const int r0 = 4 * h;

    float a0 = 0.f, a1 = 0.f, a2 = 0.f, a3 = 0.f;

    #pragma unroll 16
    for (int k = 0; k < DD; k++) {
        const float w = __ldg(&wcol[k * DD]);           // coalesced across dc
        const float4 zv = *(const float4*)&zsT[k][r0];  // broadcast LDS.128
        a0 = fmaf(zv.x, w, a0);
        a1 = fmaf(zv.y, w, a1);
        a2 = fmaf(zv.z, w, a2);
        a3 = fmaf(zv.w, w, a3);
    }

    if (is_pi) {
        const float bb = __ldg(&b1[d]);
        a0 += bb; a1 += bb; a2 += bb; a3 += bb;
        *(float4*)&g_PIBT[d * NN + i0 + r0] = make_float4(a0, a1, a2, a3);
    } else {
        *(float4*)&g_PJT[d * NN + i0 + r0] = make_float4(a0, a1, a2, a3);
    }

    // ---- fused ci/cj: stage w'*acc, then 16 warp-reductions ----
    const float wh = 0.5f * __ldg(&W2[d]);
    const int which = is_pi ? 0 : 1;
    cs[which][r0 + 0][d] = a0 * wh;
    cs[which][r0 + 1][d] = a1 * wh;
    cs[which][r0 + 2][d] = a2 * wh;
    cs[which][r0 + 3][d] = a3 * wh;
    __syncthreads();

    const int wid  = tid >> 5;           // 0..15
    const int lane = tid & 31;
    const int wch  = wid >> 3;           // 0 -> ci, 1 -> cj
    const int row  = wid & 7;
    const float4 v = *(const float4*)&cs[wch][row][lane * 4];
    float s = v.x + v.y + v.z + v.w;
    #pragma unroll
    for (int off = 16; off; off >>= 1)
        s += __shfl_down_sync(0xFFFFFFFFu, s, off);
    if (lane == 0) {
        if (wch == 0) g_ci[i0 + row] = s;
        else          g_cj[i0 + row] = s;
    }
}

// ---------------------------------------------------------------------------
// Kernel C (r9-proven d-split): partial[i,j] over d-range of 64.
// Grid (16,16,2): z selects d in [z*64,(z+1)*64) and target (out / g_P1).
// 64i x 64j tile, 256 threads (16x16), 4i x 4j per thread, f32x2 packed.
// ---------------------------------------------------------------------------
#define TPAD 68   // row stride in floats (64 + 4), keeps 16B alignment

__global__ void __launch_bounds__(256, 4) pair_kernel(float* __restrict__ out)
{
    __shared__ float pisT[DH][TPAD];            // ~17.4 KB
    __shared__ float pjs [DH][TPAD];            // ~17.4 KB
    __shared__ unsigned long long w2p[DH];      //  512 B

    const int tx  = threadIdx.x;                // 0..15 -> 4 j
    const int ty  = threadIdx.y;                // 0..15 -> 4 i
    const int tid = ty * 16 + tx;
    const int ib  = blockIdx.y * 64;
    const int jb  = blockIdx.x * 64;
    const int db  = blockIdx.z * DH;            // d-range base

    for (int idx = tid; idx < DH * 16; idx += 256) {
        const int d = idx >> 4;
        const int q = idx & 15;
        *(float4*)&pisT[d][q * 4] =
            *(const float4*)&g_PIBT[(db + d) * NN + ib + q * 4];
        *(float4*)&pjs[d][q * 4] =
            *(const float4*)&g_PJT [(db + d) * NN + jb + q * 4];
    }
    if (tid < DH) {
        const float w = g_W2H[db + tid];
        w2p[tid] = pack2(w, w);
    }
    __syncthreads();

    const int i0 = ty * 4;                      // local i base
    const int j0 = tx * 4;                      // local j base

    unsigned long long acc[2][4];               // [i-pair][j]
    #pragma unroll
    for (int p = 0; p < 2; p++)
        #pragma unroll
        for (int j = 0; j < 4; j++) acc[p][j] = 0ULL;

    #pragma unroll 4
    for (int d = 0; d < DH; d++) {
        const ulonglong2 aA = *(const ulonglong2*)&pisT[d][i0];
        const float4 bf = *(const float4*)&pjs[d][j0];
        const unsigned long long bp[4] = {
            pack2(bf.x, bf.x), pack2(bf.y, bf.y),
            pack2(bf.z, bf.z), pack2(bf.w, bf.w) };
        const unsigned long long wd = w2p[d];

        #pragma unroll
        for (int j = 0; j < 4; j++) {
            unsigned long long t0 = add2(aA.x, bp[j]) & ABS2_MASK;
            acc[0][j] = fma2(wd, t0, acc[0][j]);
            unsigned long long t1 = add2(aA.y, bp[j]) & ABS2_MASK;
            acc[1][j] = fma2(wd, t1, acc[1][j]);
        }
    }

    float* dst = (blockIdx.z == 0) ? out : g_P1;

    float v[4][4];
    #pragma unroll
    for (int p = 0; p < 2; p++)
        #pragma unroll
        for (int j = 0; j < 4; j++) {
            float lo, hi;
            unpack2(acc[p][j], lo, hi);
            v[2 * p][j]     = lo;
            v[2 * p + 1][j] = hi;
        }

    #pragma unroll
    for (int r = 0; r < 4; r++) {
        float4 o;
        o.x = v[r][0]; o.y = v[r][1]; o.z = v[r][2]; o.w = v[r][3];
        *(float4*)&dst[(ib + i0 + r) * NN + jb + j0] = o;
    }
}

// ---------------------------------------------------------------------------
// Kernel D (v3): out = out + g_P1 + ci[i] + cj[j] + b2.
// 256 blocks x 256 threads, 16 floats/thread -> 8 independent LDG.128
// (MLP 8) to cover DRAM/L2 latency; BW-bound target ~2.5us.
// ---------------------------------------------------------------------------
__global__ void __launch_bounds__(256) combine_kernel(
    const float* __restrict__ b2, float* __restrict__ out)
{
    const int idx = (blockIdx.x * 256 + threadIdx.x) * 16;
    const int i = idx >> 10;
    const int j = idx & (NN - 1);

    float4 a[4], p[4], c[4];
    #pragma unroll
    for (int t = 0; t < 4; t++) a[t] = *(float4*)&out[idx + t * 4];
    #pragma unroll
    for (int t = 0; t < 4; t++) p[t] = *(const float4*)&g_P1[idx + t * 4];
    #pragma unroll
    for (int t = 0; t < 4; t++) c[t] = *(const float4*)&g_cj[j + t * 4];
    const float base = g_ci[i] + __ldg(b2);

    #pragma unroll
    for (int t = 0; t < 4; t++) {
        a[t].x += p[t].x + c[t].x + base;
        a[t].y += p[t].y + c[t].y + base;
        a[t].z += p[t].z + c[t].z + base;
        a[t].w += p[t].w + c[t].w + base;
        *(float4*)&out[idx + t * 4] = a[t];
    }
}

// ---------------------------------------------------------------------------
// metadata order: z [1024*128], W1 [256*128], b1 [128], W2 [128], b2 [1]
// output: float32 [1024*1024]
// ---------------------------------------------------------------------------
extern "C" void kernel_launch(void* const* d_in, const int* in_sizes, int n_in,
                              void* d_out, int out_size)
{
    const float* z  = (const float*)d_in[0];
    const float* W1 = (const float*)d_in[1];
    const float* b1 = (const float*)d_in[2];
    const float* W2 = (const float*)d_in[3];
    const float* b2 = (const float*)d_in[4];
    float* out = (float*)d_out;

    prep_kernel<<<NN / 8, 512>>>(z, W1, b1, W2);

    dim3 blk(16, 16);
    dim3 grd(NN / 64, NN / 64, 2);
    pair_kernel<<<grd, blk>>>(out);

    combine_kernel<<<NN * NN / (256 * 16), 256>>>(b2, out);
}